// round 15
// baseline (speedup 1.0000x reference)
#include <cuda_runtime.h>
#include <cuda_fp16.h>
#include <cstdint>

// Path_Embedding via mma.sync m16n8k16.f16, single-f16 operands.
// Round 15: R14's gather-under-MMA overlap, but the register hold is split
// in two 20-reg windows around the two tap-passes, fitting 3 blocks/SM
// (launch_bounds(256,3), grid 444). Addressing slimmed: ab1/bb1 are constant
// offsets (+3200 / +2304), grow[] is affine (row0 + 32g).

#define VOCAB 100000
#define NPERS 444
#define RSE 160        // e-row stride bytes (+16B nudge when a odd)
#define RSW 144        // w-row stride bytes (+16B nudge when (o>>3)&1)

#define E0_OFF  0      // 160*160 = 25600
#define E1_OFF  25600
#define W_OFF   51200  // 2 taps * 64 * 144 = 18432
#define IDX_OFF 69632  // 2*160*4 = 1280
#define RED_OFF 70912  // 2*8*32*4 = 2048
#define SM_TOT  72960

typedef unsigned long long u64;

__device__ __forceinline__ uint32_t smem_u32(const void* p) {
    uint32_t a;
    asm("{ .reg .u64 t; cvta.to.shared.u64 t, %1; cvt.u32.u64 %0, t; }" : "=r"(a) : "l"(p));
    return a;
}

#define LDMX4(r, addr)                                                        \
    asm volatile("ldmatrix.sync.aligned.m8n8.x4.shared.b16 {%0,%1,%2,%3}, [%4];" \
        : "=r"((r)[0]), "=r"((r)[1]), "=r"((r)[2]), "=r"((r)[3]) : "r"(addr))

#define MMA(d, a, b0, b1)                                                     \
    asm volatile("mma.sync.aligned.m16n8k16.row.col.f32.f16.f16.f32 "         \
        "{%0,%1,%2,%3},{%4,%5,%6,%7},{%8,%9},{%0,%1,%2,%3};"                  \
        : "+f"((d)[0]), "+f"((d)[1]), "+f"((d)[2]), "+f"((d)[3])              \
        : "r"((a)[0]), "r"((a)[1]), "r"((a)[2]), "r"((a)[3]),                 \
          "r"(b0), "r"(b1))

__device__ __forceinline__ u64 pack4(float x, float y, float z, float w) {
    __half2 h01 = __float22half2_rn(make_float2(x, y));
    __half2 h23 = __float22half2_rn(make_float2(z, w));
    uint32_t h0 = *reinterpret_cast<uint32_t*>(&h01);
    uint32_t h1 = *reinterpret_cast<uint32_t*>(&h23);
    return (u64)h0 | ((u64)h1 << 32);
}

// one tap-pass of MMA (4 k-steps), B slices at +0 and +2304, A at +0/+3200
__device__ __forceinline__ void mma_tap(float d[2][4][4], uint32_t aE,
                                        uint32_t bW) {
    #pragma unroll
    for (int ks = 0; ks < 4; ks++) {
        const uint32_t kb = (uint32_t)(ks * 32);
        uint32_t a0[4], a1[4], b0[4], b1[4];
        LDMX4(a0, aE + kb);
        LDMX4(a1, aE + kb + 3200);           // m+16 slice: +20 rows
        LDMX4(b0, bW + kb);
        LDMX4(b1, bW + kb + 2304);           // n+16 slice: +16 w-rows
        MMA(d[0][0], a0, b0[0], b0[1]);
        MMA(d[0][1], a0, b0[2], b0[3]);
        MMA(d[0][2], a0, b1[0], b1[1]);
        MMA(d[0][3], a0, b1[2], b1[3]);
        MMA(d[1][0], a1, b0[0], b0[1]);
        MMA(d[1][1], a1, b0[2], b0[3]);
        MMA(d[1][2], a1, b1[0], b1[1]);
        MMA(d[1][3], a1, b1[2], b1[3]);
    }
}

__global__ __launch_bounds__(256, 3) void path_emb_hmma(
    const int*   __restrict__ path_input,   // [8192,16,5]
    const int*   __restrict__ path_type,    // [5]
    const float* __restrict__ tables,       // [3,100000,64]
    const float* __restrict__ conv_w,       // [64,64,2]
    const float* __restrict__ conv_b,       // [64]
    float*       __restrict__ out)          // [8192,64]
{
    extern __shared__ char smem[];
    const uint32_t sb = smem_u32(smem);
    const int tid  = threadIdx.x;
    const int lane = tid & 31;
    const int wid  = tid >> 5;
    const int mgrp = wid & 3;
    const int ngrp = wid >> 2;

    int (*idx_s)[160]   = reinterpret_cast<int(*)[160]>(smem + IDX_OFF);
    float (*red)[8][32] = reinterpret_cast<float(*)[8][32]>(smem + RED_OFF);
    const float4* tab4  = reinterpret_cast<const float4*>(tables);

    // ---- stage W once per block ----
    {
        const float2* cw2 = reinterpret_cast<const float2*>(conv_w);
        #pragma unroll
        for (int it = 0; it < 16; it++) {
            int i = tid + it * 256;          // i = o*64 + j
            int o = i >> 6, j = i & 63;
            float2 wv = cw2[i];
            int ob = o * RSW + (((o >> 3) & 1) << 4) + j * 2;
            *reinterpret_cast<__half*>(smem + W_OFF + ob)        = __float2half_rn(wv.x);
            *reinterpret_cast<__half*>(smem + W_OFF + 9216 + ob) = __float2half_rn(wv.y);
        }
    }

    // ---- gather addressing: row = row0 + 32g (affine), offsets precomputed ----
    const int row0 = tid >> 3;
    const int qq   = tid & 7;
    uint32_t goff[5];
    #pragma unroll
    for (int g = 0; g < 5; g++) {
        int row = row0 + 32 * g;
        int a = (row % 80) / 5;
        goff[g] = (uint32_t)(row * RSE + ((a & 1) << 4) + qq * 16);
    }

    // ---- idx-staging params (tid < 160) ----
    int ib_a = 0, ib_t = 0, ib_b2 = 0, ib_type = 0;
    if (tid < 160) {
        int b2 = tid / 80, rr = tid % 80;
        ib_a = rr / 5; ib_t = rr % 5; ib_b2 = b2;
        ib_type = __ldg(&path_type[ib_t]) * VOCAB;
    }

    // ---- epilogue params (tid < 128) ----
    float bias = 0.f; int ob2 = 0, oc = 0, ow1 = 0, occ_ = 0;
    if (tid < 128) {
        ob2 = tid >> 6; oc = tid & 63;
        ow1 = (oc >> 5) * 4 + ob2 * 2; occ_ = oc & 31;
        bias = __ldg(&conv_b[oc]);
    }

    // ---- ldmatrix lane base addresses (slices are constant offsets) ----
    uint32_t ab0, bb0;
    {
        int m  = mgrp * 32 + (lane & 15);
        int b2 = mgrp >> 1;
        int aa = (m >> 2) & 15, w = m & 3;
        ab0 = (uint32_t)((b2 * 80 + aa * 5 + w) * RSE + ((aa & 1) << 4)
                         + ((lane >> 4) << 4));
        int nr = ngrp * 32 + (lane & 7) + ((lane >> 4) << 3);
        bb0 = (uint32_t)(nr * RSW + (((nr >> 3) & 1) << 4) + (((lane >> 3) & 1) << 4));
    }

    // ---- prologue: idx[0](tile0) -> gather E0; idx[1](tile0+NPERS) ----
    const int tile0 = blockIdx.x;
    if (tid < 160) {
        int b = tile0 * 2 + ib_b2, p = b & 15, nb = b >> 4;
        idx_s[0][tid] = ib_type + path_input[(((ib_a << 9) + nb) * 16 + p) * 5 + ib_t];
    }
    __syncthreads();
    #pragma unroll
    for (int g = 0; g < 5; g++) {
        long long rbase = (long long)idx_s[0][row0 + 32 * g] * 16 + qq * 2;
        float4 va = __ldg(&tab4[rbase]);
        float4 vb = __ldg(&tab4[rbase + 1]);
        ulonglong2 hv;
        hv.x = pack4(va.x, va.y, va.z, va.w);
        hv.y = pack4(vb.x, vb.y, vb.z, vb.w);
        *reinterpret_cast<ulonglong2*>(smem + E0_OFF + goff[g]) = hv;
    }
    if (tid < 160 && tile0 + NPERS < 4096) {
        int b = (tile0 + NPERS) * 2 + ib_b2, p = b & 15, nb = b >> 4;
        idx_s[1][tid] = ib_type + path_input[(((ib_a << 9) + nb) * 16 + p) * 5 + ib_t];
    }
    __syncthreads();

    int n = 0;
    for (int tile = tile0; tile < 4096; tile += NPERS, n++) {
        const int  fr  = n & 1;
        const int  bk  = fr ^ 1;
        const bool nx  = tile + NPERS     < 4096;
        const bool nx2 = tile + 2 * NPERS < 4096;
        const uint32_t eF = fr ? E1_OFF : E0_OFF;
        const uint32_t eB = fr ? E0_OFF : E1_OFF;

        float d[2][4][4];
        #pragma unroll
        for (int mt = 0; mt < 2; mt++)
            #pragma unroll
            for (int nt = 0; nt < 4; nt++)
                #pragma unroll
                for (int r = 0; r < 4; r++) d[mt][nt][r] = 0.f;

        // ---- 1a. issue first-half gather LDGs (20 regs held) ----
        float4 va[5];
        if (nx) {
            #pragma unroll
            for (int g = 0; g < 5; g++)
                va[g] = __ldg(&tab4[(long long)idx_s[bk][row0 + 32 * g] * 16 + qq * 2]);
        }
        // ---- 1b. prefetch idx(tile + 2*NPERS) ----
        int ridx = 0;
        if (tid < 160 && nx2) {
            int b = (tile + 2 * NPERS) * 2 + ib_b2, p = b & 15, nb = b >> 4;
            ridx = ib_type + path_input[(((ib_a << 9) + nb) * 16 + p) * 5 + ib_t];
        }

        // ---- 2. MMA tap0 (covers va flight) ----
        mma_tap(d, sb + eF + ab0, sb + W_OFF + bb0);

        // ---- 3. pack + STS va ----
        if (nx) {
            #pragma unroll
            for (int g = 0; g < 5; g++)
                *reinterpret_cast<u64*>(smem + eB + goff[g])
                    = pack4(va[g].x, va[g].y, va[g].z, va[g].w);
        }
        // ---- 4. issue second-half gather LDGs ----
        float4 vb[5];
        if (nx) {
            #pragma unroll
            for (int g = 0; g < 5; g++)
                vb[g] = __ldg(&tab4[(long long)idx_s[bk][row0 + 32 * g] * 16 + qq * 2 + 1]);
        }

        // ---- 5. MMA tap1 (covers vb flight) ----
        mma_tap(d, sb + eF + ab0 + RSE, sb + W_OFF + 9216 + bb0);

        // ---- 6. warp-local max over 32 m-rows -> red[fr][wid] ----
        #pragma unroll
        for (int nt = 0; nt < 4; nt++) {
            float v0 = fmaxf(fmaxf(d[0][nt][0], d[0][nt][2]),
                             fmaxf(d[1][nt][0], d[1][nt][2]));
            float v1 = fmaxf(fmaxf(d[0][nt][1], d[0][nt][3]),
                             fmaxf(d[1][nt][1], d[1][nt][3]));
            #pragma unroll
            for (int mask = 4; mask <= 16; mask <<= 1) {
                v0 = fmaxf(v0, __shfl_xor_sync(0xffffffffu, v0, mask));
                v1 = fmaxf(v1, __shfl_xor_sync(0xffffffffu, v1, mask));
            }
            if (lane < 4) {
                red[fr][wid][nt * 8 + lane * 2]     = v0;
                red[fr][wid][nt * 8 + lane * 2 + 1] = v1;
            }
        }

        // ---- 7. pack + STS vb; stage idx ----
        if (nx) {
            #pragma unroll
            for (int g = 0; g < 5; g++)
                *reinterpret_cast<u64*>(smem + eB + goff[g] + 8)
                    = pack4(vb[g].x, vb[g].y, vb[g].z, vb[g].w);
        }
        if (tid < 160 && nx2) idx_s[fr][tid] = ridx;

        __syncthreads();

        // ---- 8. store this tile's output ----
        if (tid < 128) {
            float m = fmaxf(red[fr][ow1][occ_], red[fr][ow1 + 1][occ_]);
            out[(long long)(tile * 2 + ob2) * 64 + oc] = m + bias;
        }
    }
}

extern "C" void kernel_launch(void* const* d_in, const int* in_sizes, int n_in,
                              void* d_out, int out_size) {
    const int*   path_input = (const int*)d_in[0];
    const int*   path_type  = (const int*)d_in[1];
    const float* tables     = (const float*)d_in[2];
    const float* conv_w     = (const float*)d_in[3];
    const float* conv_b     = (const float*)d_in[4];
    float* out = (float*)d_out;

    cudaFuncSetAttribute(path_emb_hmma,
                         cudaFuncAttributeMaxDynamicSharedMemorySize, SM_TOT);

    path_emb_hmma<<<NPERS, 256, SM_TOT>>>(path_input, path_type, tables,
                                          conv_w, conv_b, out);
}

// round 16
// speedup vs baseline: 1.1261x; 1.1261x over previous
#include <cuda_runtime.h>
#include <cuda_fp16.h>
#include <cstdint>

// Path_Embedding via mma.sync m16n8k16.f16, single-f16 operands.
// Round 16: gather-under-MMA overlap (R14's proven mechanism) at 3 blocks/SM,
// with the register hold split by ROWS (not q-pairs, R15's failure): batch A
// = 2 rows (16 regs) covered by MMA tap0, batch B = 3 rows (24 regs) covered
// by tap1. Each row's 32B is loaded in one line visit and stored as one 16B
// STS, exactly like R10. Slim addressing (+3200/+2304 slice constants).

#define VOCAB 100000
#define NPERS 444
#define RSE 160        // e-row stride bytes (+16B nudge when a odd)
#define RSW 144        // w-row stride bytes (+16B nudge when (o>>3)&1)

#define E0_OFF  0      // 160*160 = 25600
#define E1_OFF  25600
#define W_OFF   51200  // 2 taps * 64 * 144 = 18432
#define IDX_OFF 69632  // 2*160*4 = 1280
#define RED_OFF 70912  // 2*8*32*4 = 2048
#define SM_TOT  72960

typedef unsigned long long u64;

__device__ __forceinline__ uint32_t smem_u32(const void* p) {
    uint32_t a;
    asm("{ .reg .u64 t; cvta.to.shared.u64 t, %1; cvt.u32.u64 %0, t; }" : "=r"(a) : "l"(p));
    return a;
}

#define LDMX4(r, addr)                                                        \
    asm volatile("ldmatrix.sync.aligned.m8n8.x4.shared.b16 {%0,%1,%2,%3}, [%4];" \
        : "=r"((r)[0]), "=r"((r)[1]), "=r"((r)[2]), "=r"((r)[3]) : "r"(addr))

#define MMA(d, a, b0, b1)                                                     \
    asm volatile("mma.sync.aligned.m16n8k16.row.col.f32.f16.f16.f32 "         \
        "{%0,%1,%2,%3},{%4,%5,%6,%7},{%8,%9},{%0,%1,%2,%3};"                  \
        : "+f"((d)[0]), "+f"((d)[1]), "+f"((d)[2]), "+f"((d)[3])              \
        : "r"((a)[0]), "r"((a)[1]), "r"((a)[2]), "r"((a)[3]),                 \
          "r"(b0), "r"(b1))

__device__ __forceinline__ u64 pack4(float x, float y, float z, float w) {
    __half2 h01 = __float22half2_rn(make_float2(x, y));
    __half2 h23 = __float22half2_rn(make_float2(z, w));
    uint32_t h0 = *reinterpret_cast<uint32_t*>(&h01);
    uint32_t h1 = *reinterpret_cast<uint32_t*>(&h23);
    return (u64)h0 | ((u64)h1 << 32);
}

// one tap-pass of MMA (4 k-steps); slices at constant offsets
// (A m+16 slice: +20 e-rows = +3200B; B n+16 slice: +16 w-rows = +2304B;
//  both preserve the swizzle-nudge parity — verified)
__device__ __forceinline__ void mma_tap(float d[2][4][4], uint32_t aE,
                                        uint32_t bW) {
    #pragma unroll
    for (int ks = 0; ks < 4; ks++) {
        const uint32_t kb = (uint32_t)(ks * 32);
        uint32_t a0[4], a1[4], b0[4], b1[4];
        LDMX4(a0, aE + kb);
        LDMX4(a1, aE + kb + 3200);
        LDMX4(b0, bW + kb);
        LDMX4(b1, bW + kb + 2304);
        MMA(d[0][0], a0, b0[0], b0[1]);
        MMA(d[0][1], a0, b0[2], b0[3]);
        MMA(d[0][2], a0, b1[0], b1[1]);
        MMA(d[0][3], a0, b1[2], b1[3]);
        MMA(d[1][0], a1, b0[0], b0[1]);
        MMA(d[1][1], a1, b0[2], b0[3]);
        MMA(d[1][2], a1, b1[0], b1[1]);
        MMA(d[1][3], a1, b1[2], b1[3]);
    }
}

__global__ __launch_bounds__(256, 3) void path_emb_hmma(
    const int*   __restrict__ path_input,   // [8192,16,5]
    const int*   __restrict__ path_type,    // [5]
    const float* __restrict__ tables,       // [3,100000,64]
    const float* __restrict__ conv_w,       // [64,64,2]
    const float* __restrict__ conv_b,       // [64]
    float*       __restrict__ out)          // [8192,64]
{
    extern __shared__ char smem[];
    const uint32_t sb = smem_u32(smem);
    const int tid  = threadIdx.x;
    const int lane = tid & 31;
    const int wid  = tid >> 5;
    const int mgrp = wid & 3;
    const int ngrp = wid >> 2;

    int (*idx_s)[160]   = reinterpret_cast<int(*)[160]>(smem + IDX_OFF);
    float (*red)[8][32] = reinterpret_cast<float(*)[8][32]>(smem + RED_OFF);
    const float4* tab4  = reinterpret_cast<const float4*>(tables);

    // ---- stage W once per block ----
    {
        const float2* cw2 = reinterpret_cast<const float2*>(conv_w);
        #pragma unroll
        for (int it = 0; it < 16; it++) {
            int i = tid + it * 256;          // i = o*64 + j
            int o = i >> 6, j = i & 63;
            float2 wv = cw2[i];
            int ob = o * RSW + (((o >> 3) & 1) << 4) + j * 2;
            *reinterpret_cast<__half*>(smem + W_OFF + ob)        = __float2half_rn(wv.x);
            *reinterpret_cast<__half*>(smem + W_OFF + 9216 + ob) = __float2half_rn(wv.y);
        }
    }

    // ---- gather addressing: row = row0 + 32g (affine) ----
    const int row0 = tid >> 3;
    const int qq   = tid & 7;
    uint32_t goff[5];
    #pragma unroll
    for (int g = 0; g < 5; g++) {
        int row = row0 + 32 * g;
        int a = (row % 80) / 5;
        goff[g] = (uint32_t)(row * RSE + ((a & 1) << 4) + qq * 16);
    }

    // ---- idx-staging params (tid < 160) ----
    int ib_a = 0, ib_t = 0, ib_b2 = 0, ib_type = 0;
    if (tid < 160) {
        int b2 = tid / 80, rr = tid % 80;
        ib_a = rr / 5; ib_t = rr % 5; ib_b2 = b2;
        ib_type = __ldg(&path_type[ib_t]) * VOCAB;
    }

    // ---- epilogue params (tid < 128) ----
    float bias = 0.f; int ob2 = 0, oc = 0, ow1 = 0, occ_ = 0;
    if (tid < 128) {
        ob2 = tid >> 6; oc = tid & 63;
        ow1 = (oc >> 5) * 4 + ob2 * 2; occ_ = oc & 31;
        bias = __ldg(&conv_b[oc]);
    }

    // ---- ldmatrix lane base addresses ----
    uint32_t ab0, bb0;
    {
        int m  = mgrp * 32 + (lane & 15);
        int b2 = mgrp >> 1;
        int aa = (m >> 2) & 15, w = m & 3;
        ab0 = (uint32_t)((b2 * 80 + aa * 5 + w) * RSE + ((aa & 1) << 4)
                         + ((lane >> 4) << 4));
        int nr = ngrp * 32 + (lane & 7) + ((lane >> 4) << 3);
        bb0 = (uint32_t)(nr * RSW + (((nr >> 3) & 1) << 4) + (((lane >> 3) & 1) << 4));
    }

    // ---- prologue: idx[0](tile0) -> gather E0; idx[1](tile0+NPERS) ----
    const int tile0 = blockIdx.x;
    if (tid < 160) {
        int b = tile0 * 2 + ib_b2, p = b & 15, nb = b >> 4;
        idx_s[0][tid] = ib_type + path_input[(((ib_a << 9) + nb) * 16 + p) * 5 + ib_t];
    }
    __syncthreads();
    #pragma unroll
    for (int g = 0; g < 5; g++) {
        long long rbase = (long long)idx_s[0][row0 + 32 * g] * 16 + qq * 2;
        float4 va = __ldg(&tab4[rbase]);
        float4 vb = __ldg(&tab4[rbase + 1]);
        ulonglong2 hv;
        hv.x = pack4(va.x, va.y, va.z, va.w);
        hv.y = pack4(vb.x, vb.y, vb.z, vb.w);
        *reinterpret_cast<ulonglong2*>(smem + E0_OFF + goff[g]) = hv;
    }
    if (tid < 160 && tile0 + NPERS < 4096) {
        int b = (tile0 + NPERS) * 2 + ib_b2, p = b & 15, nb = b >> 4;
        idx_s[1][tid] = ib_type + path_input[(((ib_a << 9) + nb) * 16 + p) * 5 + ib_t];
    }
    __syncthreads();

    int n = 0;
    for (int tile = tile0; tile < 4096; tile += NPERS, n++) {
        const int  fr  = n & 1;
        const int  bk  = fr ^ 1;
        const bool nx  = tile + NPERS     < 4096;
        const bool nx2 = tile + 2 * NPERS < 4096;
        const uint32_t eF = fr ? E1_OFF : E0_OFF;
        const uint32_t eB = fr ? E0_OFF : E1_OFF;

        float d[2][4][4];
        #pragma unroll
        for (int mt = 0; mt < 2; mt++)
            #pragma unroll
            for (int nt = 0; nt < 4; nt++)
                #pragma unroll
                for (int r = 0; r < 4; r++) d[mt][nt][r] = 0.f;

        // ---- 1a. issue batch-A gather LDGs: rows g=0,1 (16 regs held) ----
        float4 vA[2][2];
        if (nx) {
            #pragma unroll
            for (int g = 0; g < 2; g++) {
                long long rbase = (long long)idx_s[bk][row0 + 32 * g] * 16 + qq * 2;
                vA[g][0] = __ldg(&tab4[rbase]);
                vA[g][1] = __ldg(&tab4[rbase + 1]);
            }
        }
        // ---- 1b. prefetch idx(tile + 2*NPERS) ----
        int ridx = 0;
        if (tid < 160 && nx2) {
            int b = (tile + 2 * NPERS) * 2 + ib_b2, p = b & 15, nb = b >> 4;
            ridx = ib_type + path_input[(((ib_a << 9) + nb) * 16 + p) * 5 + ib_t];
        }

        // ---- 2. MMA tap0 (covers batch A) ----
        mma_tap(d, sb + eF + ab0, sb + W_OFF + bb0);

        // ---- 3. pack + STS batch A (one 16B store per row, as in R10) ----
        if (nx) {
            #pragma unroll
            for (int g = 0; g < 2; g++) {
                ulonglong2 hv;
                hv.x = pack4(vA[g][0].x, vA[g][0].y, vA[g][0].z, vA[g][0].w);
                hv.y = pack4(vA[g][1].x, vA[g][1].y, vA[g][1].z, vA[g][1].w);
                *reinterpret_cast<ulonglong2*>(smem + eB + goff[g]) = hv;
            }
        }
        // ---- 4. issue batch-B gather LDGs: rows g=2,3,4 (24 regs held) ----
        float4 vB[3][2];
        if (nx) {
            #pragma unroll
            for (int g = 0; g < 3; g++) {
                long long rbase = (long long)idx_s[bk][row0 + 32 * (g + 2)] * 16 + qq * 2;
                vB[g][0] = __ldg(&tab4[rbase]);
                vB[g][1] = __ldg(&tab4[rbase + 1]);
            }
        }

        // ---- 5. MMA tap1 (covers batch B) ----
        mma_tap(d, sb + eF + ab0 + RSE, sb + W_OFF + 9216 + bb0);

        // ---- 6. warp-local max over 32 m-rows -> red[fr][wid] ----
        #pragma unroll
        for (int nt = 0; nt < 4; nt++) {
            float v0 = fmaxf(fmaxf(d[0][nt][0], d[0][nt][2]),
                             fmaxf(d[1][nt][0], d[1][nt][2]));
            float v1 = fmaxf(fmaxf(d[0][nt][1], d[0][nt][3]),
                             fmaxf(d[1][nt][1], d[1][nt][3]));
            #pragma unroll
            for (int mask = 4; mask <= 16; mask <<= 1) {
                v0 = fmaxf(v0, __shfl_xor_sync(0xffffffffu, v0, mask));
                v1 = fmaxf(v1, __shfl_xor_sync(0xffffffffu, v1, mask));
            }
            if (lane < 4) {
                red[fr][wid][nt * 8 + lane * 2]     = v0;
                red[fr][wid][nt * 8 + lane * 2 + 1] = v1;
            }
        }

        // ---- 7. pack + STS batch B; stage idx ----
        if (nx) {
            #pragma unroll
            for (int g = 0; g < 3; g++) {
                ulonglong2 hv;
                hv.x = pack4(vB[g][0].x, vB[g][0].y, vB[g][0].z, vB[g][0].w);
                hv.y = pack4(vB[g][1].x, vB[g][1].y, vB[g][1].z, vB[g][1].w);
                *reinterpret_cast<ulonglong2*>(smem + eB + goff[g + 2]) = hv;
            }
        }
        if (tid < 160 && nx2) idx_s[fr][tid] = ridx;

        __syncthreads();

        // ---- 8. store this tile's output ----
        if (tid < 128) {
            float m = fmaxf(red[fr][ow1][occ_], red[fr][ow1 + 1][occ_]);
            out[(long long)(tile * 2 + ob2) * 64 + oc] = m + bias;
        }
    }
}

extern "C" void kernel_launch(void* const* d_in, const int* in_sizes, int n_in,
                              void* d_out, int out_size) {
    const int*   path_input = (const int*)d_in[0];
    const int*   path_type  = (const int*)d_in[1];
    const float* tables     = (const float*)d_in[2];
    const float* conv_w     = (const float*)d_in[3];
    const float* conv_b     = (const float*)d_in[4];
    float* out = (float*)d_out;

    cudaFuncSetAttribute(path_emb_hmma,
                         cudaFuncAttributeMaxDynamicSharedMemorySize, SM_TOT);

    path_emb_hmma<<<NPERS, 256, SM_TOT>>>(path_input, path_type, tables,
                                          conv_w, conv_b, out);
}

// round 17
// speedup vs baseline: 1.2139x; 1.0780x over previous
#include <cuda_runtime.h>
#include <cuda_fp16.h>
#include <cstdint>

// Path_Embedding via mma.sync m16n8k16.f16, single-f16 operands.
// Round 17: WARP SPECIALIZATION. 384 threads: warps 0-7 = consumers (R10's
// exact MMA + epilogue, zero LDG in steady state), warps 8-11 = producers
// (gather LDG->pack->STS + idx staging; their stalls are covered by consumer
// warps on the same SMSPs). One barrier/tile, R10's double-buffer protocol.
// 2 blocks/SM (24 warps/SM, same as R10) but the consumer critical path
// drops the entire gather.

#define VOCAB 100000
#define NPERS 296
#define RSE 160        // e-row stride bytes (+16B nudge when a odd)
#define RSW 144        // w-row stride bytes (+16B nudge when (o>>3)&1)

#define E0_OFF  0      // 160*160 = 25600
#define E1_OFF  25600
#define W_OFF   51200  // 2 taps * 64 * 144 = 18432
#define IDX_OFF 69632  // 2*160*4 = 1280
#define RED_OFF 70912  // 2*8*32*4 = 2048
#define SM_TOT  72960

typedef unsigned long long u64;

__device__ __forceinline__ uint32_t smem_u32(const void* p) {
    uint32_t a;
    asm("{ .reg .u64 t; cvta.to.shared.u64 t, %1; cvt.u32.u64 %0, t; }" : "=r"(a) : "l"(p));
    return a;
}

#define LDMX4(r, addr)                                                        \
    asm volatile("ldmatrix.sync.aligned.m8n8.x4.shared.b16 {%0,%1,%2,%3}, [%4];" \
        : "=r"((r)[0]), "=r"((r)[1]), "=r"((r)[2]), "=r"((r)[3]) : "r"(addr))

#define MMA(d, a, b0, b1)                                                     \
    asm volatile("mma.sync.aligned.m16n8k16.row.col.f32.f16.f16.f32 "         \
        "{%0,%1,%2,%3},{%4,%5,%6,%7},{%8,%9},{%0,%1,%2,%3};"                  \
        : "+f"((d)[0]), "+f"((d)[1]), "+f"((d)[2]), "+f"((d)[3])              \
        : "r"((a)[0]), "r"((a)[1]), "r"((a)[2]), "r"((a)[3]),                 \
          "r"(b0), "r"(b1))

__device__ __forceinline__ u64 pack4(float x, float y, float z, float w) {
    __half2 h01 = __float22half2_rn(make_float2(x, y));
    __half2 h23 = __float22half2_rn(make_float2(z, w));
    uint32_t h0 = *reinterpret_cast<uint32_t*>(&h01);
    uint32_t h1 = *reinterpret_cast<uint32_t*>(&h23);
    return (u64)h0 | ((u64)h1 << 32);
}

__global__ __launch_bounds__(384, 2) void path_emb_hmma(
    const int*   __restrict__ path_input,   // [8192,16,5]
    const int*   __restrict__ path_type,    // [5]
    const float* __restrict__ tables,       // [3,100000,64]
    const float* __restrict__ conv_w,       // [64,64,2]
    const float* __restrict__ conv_b,       // [64]
    float*       __restrict__ out)          // [8192,64]
{
    extern __shared__ char smem[];
    const uint32_t sb = smem_u32(smem);
    const int tid  = threadIdx.x;
    const int lane = tid & 31;
    const int wid  = tid >> 5;
    const bool consumer = (tid < 256);
    const int ptid = tid - 256;              // producer thread id, 0..127

    int (*idx_s)[160]   = reinterpret_cast<int(*)[160]>(smem + IDX_OFF);
    float (*red)[8][32] = reinterpret_cast<float(*)[8][32]>(smem + RED_OFF);
    const float4* tab4  = reinterpret_cast<const float4*>(tables);

    // ---- stage W once per block (all 384 threads) ----
    {
        const float2* cw2 = reinterpret_cast<const float2*>(conv_w);
        for (int i = tid; i < 4096; i += 384) {
            int o = i >> 6, j = i & 63;
            float2 wv = cw2[i];
            int ob = o * RSW + (((o >> 3) & 1) << 4) + j * 2;
            *reinterpret_cast<__half*>(smem + W_OFF + ob)        = __float2half_rn(wv.x);
            *reinterpret_cast<__half*>(smem + W_OFF + 9216 + ob) = __float2half_rn(wv.y);
        }
    }

    // ======================= producer-only invariants =======================
    // gather: unit k = ptid + 128g (g<10), row = (ptid>>3) + 16g, qq = ptid&7
    const int row0p = consumer ? 0 : (ptid >> 3);
    const int qq    = consumer ? 0 : (ptid & 7);
    uint32_t goff[10];
    if (!consumer) {
        #pragma unroll
        for (int g = 0; g < 10; g++) {
            int row = row0p + 16 * g;
            int a = (row % 80) / 5;
            goff[g] = (uint32_t)(row * RSE + ((a & 1) << 4) + qq * 16);
        }
    }
    // idx staging: thread handles r1 = ptid, and r2 = ptid+128 (if < 160)
    int i1_a = 0, i1_t5 = 0, i1_b2 = 0, i1_ty = 0;
    int i2_a = 0, i2_t5 = 0, i2_b2 = 0, i2_ty = 0;
    bool has2 = false;
    if (!consumer) {
        int r = ptid;
        i1_b2 = r / 80; int rr = r % 80; i1_a = rr / 5; i1_t5 = rr % 5;
        i1_ty = __ldg(&path_type[i1_t5]) * VOCAB;
        has2 = (ptid + 128) < 160;
        if (has2) {
            r = ptid + 128;
            i2_b2 = r / 80; rr = r % 80; i2_a = rr / 5; i2_t5 = rr % 5;
            i2_ty = __ldg(&path_type[i2_t5]) * VOCAB;
        }
    }

    // ======================= consumer-only invariants =======================
    uint32_t ab0 = 0, bb0 = 0;
    float bias = 0.f; int ob2 = 0, oc = 0, ow1 = 0, occ_ = 0;
    if (consumer) {
        const int mgrp = wid & 3, ngrp = wid >> 2;
        int m  = mgrp * 32 + (lane & 15);
        int b2 = mgrp >> 1;
        int aa = (m >> 2) & 15, w = m & 3;
        ab0 = (uint32_t)((b2 * 80 + aa * 5 + w) * RSE + ((aa & 1) << 4)
                         + ((lane >> 4) << 4));
        int nr = ngrp * 32 + (lane & 7) + ((lane >> 4) << 3);
        bb0 = (uint32_t)(nr * RSW + (((nr >> 3) & 1) << 4) + (((lane >> 3) & 1) << 4));
        if (tid < 128) {
            ob2 = tid >> 6; oc = tid & 63;
            ow1 = (oc >> 5) * 4 + ob2 * 2; occ_ = oc & 31;
            bias = __ldg(&conv_b[oc]);
        }
    }

    // ---- prologue (producers): idx[0](tile0) -> gather E0; idx[1](+NPERS) ----
    const int tile0 = blockIdx.x;
    if (!consumer) {
        int b = tile0 * 2 + i1_b2, p = b & 15, nb = b >> 4;
        idx_s[0][ptid] = i1_ty + path_input[(((i1_a << 9) + nb) * 16 + p) * 5 + i1_t5];
        if (has2) {
            b = tile0 * 2 + i2_b2; p = b & 15; nb = b >> 4;
            idx_s[0][ptid + 128] = i2_ty
                + path_input[(((i2_a << 9) + nb) * 16 + p) * 5 + i2_t5];
        }
    }
    __syncthreads();
    if (!consumer) {
        #pragma unroll
        for (int g = 0; g < 10; g++) {
            long long rbase = (long long)idx_s[0][row0p + 16 * g] * 16 + qq * 2;
            float4 va = __ldg(&tab4[rbase]);
            float4 vb = __ldg(&tab4[rbase + 1]);
            ulonglong2 hv;
            hv.x = pack4(va.x, va.y, va.z, va.w);
            hv.y = pack4(vb.x, vb.y, vb.z, vb.w);
            *reinterpret_cast<ulonglong2*>(smem + E0_OFF + goff[g]) = hv;
        }
        if (tile0 + NPERS < 4096) {
            int b = (tile0 + NPERS) * 2 + i1_b2, p = b & 15, nb = b >> 4;
            idx_s[1][ptid] = i1_ty
                + path_input[(((i1_a << 9) + nb) * 16 + p) * 5 + i1_t5];
            if (has2) {
                b = (tile0 + NPERS) * 2 + i2_b2; p = b & 15; nb = b >> 4;
                idx_s[1][ptid + 128] = i2_ty
                    + path_input[(((i2_a << 9) + nb) * 16 + p) * 5 + i2_t5];
            }
        }
    }
    __syncthreads();

    int n = 0;
    for (int tile = tile0; tile < 4096; tile += NPERS, n++) {
        const int  fr  = n & 1;
        const int  bk  = fr ^ 1;
        const bool nx  = tile + NPERS     < 4096;
        const bool nx2 = tile + 2 * NPERS < 4096;
        const uint32_t eF = fr ? E1_OFF : E0_OFF;
        const uint32_t eB = fr ? E0_OFF : E1_OFF;

        if (consumer) {
            // ================== consumer: MMA + epilogue ==================
            float d[2][4][4];
            #pragma unroll
            for (int mt = 0; mt < 2; mt++)
                #pragma unroll
                for (int nt = 0; nt < 4; nt++)
                    #pragma unroll
                    for (int r = 0; r < 4; r++) d[mt][nt][r] = 0.f;

            #pragma unroll
            for (int tap = 0; tap < 2; tap++) {
                const uint32_t aE = sb + eF + ab0 + tap * RSE;
                const uint32_t bW = sb + W_OFF + tap * 9216 + bb0;
                #pragma unroll
                for (int ks = 0; ks < 4; ks++) {
                    const uint32_t kb = (uint32_t)(ks * 32);
                    uint32_t a0[4], a1[4], b0[4], b1[4];
                    LDMX4(a0, aE + kb);
                    LDMX4(a1, aE + kb + 3200);   // m+16 slice (+20 e-rows)
                    LDMX4(b0, bW + kb);
                    LDMX4(b1, bW + kb + 2304);   // n+16 slice (+16 w-rows)
                    MMA(d[0][0], a0, b0[0], b0[1]);
                    MMA(d[0][1], a0, b0[2], b0[3]);
                    MMA(d[0][2], a0, b1[0], b1[1]);
                    MMA(d[0][3], a0, b1[2], b1[3]);
                    MMA(d[1][0], a1, b0[0], b0[1]);
                    MMA(d[1][1], a1, b0[2], b0[3]);
                    MMA(d[1][2], a1, b1[0], b1[1]);
                    MMA(d[1][3], a1, b1[2], b1[3]);
                }
            }

            #pragma unroll
            for (int nt = 0; nt < 4; nt++) {
                float v0 = fmaxf(fmaxf(d[0][nt][0], d[0][nt][2]),
                                 fmaxf(d[1][nt][0], d[1][nt][2]));
                float v1 = fmaxf(fmaxf(d[0][nt][1], d[0][nt][3]),
                                 fmaxf(d[1][nt][1], d[1][nt][3]));
                #pragma unroll
                for (int mask = 4; mask <= 16; mask <<= 1) {
                    v0 = fmaxf(v0, __shfl_xor_sync(0xffffffffu, v0, mask));
                    v1 = fmaxf(v1, __shfl_xor_sync(0xffffffffu, v1, mask));
                }
                if (lane < 4) {
                    red[fr][wid][nt * 8 + lane * 2]     = v0;
                    red[fr][wid][nt * 8 + lane * 2 + 1] = v1;
                }
            }
        } else {
            // ================== producer: gather + idx staging ==============
            if (nx) {
                #pragma unroll
                for (int g = 0; g < 10; g++) {
                    long long rbase =
                        (long long)idx_s[bk][row0p + 16 * g] * 16 + qq * 2;
                    float4 va = __ldg(&tab4[rbase]);
                    float4 vb = __ldg(&tab4[rbase + 1]);
                    ulonglong2 hv;
                    hv.x = pack4(va.x, va.y, va.z, va.w);
                    hv.y = pack4(vb.x, vb.y, vb.z, vb.w);
                    *reinterpret_cast<ulonglong2*>(smem + eB + goff[g]) = hv;
                }
            }
            if (nx2) {
                int t2 = tile + 2 * NPERS;
                int b = t2 * 2 + i1_b2, p = b & 15, nb = b >> 4;
                idx_s[fr][ptid] = i1_ty
                    + path_input[(((i1_a << 9) + nb) * 16 + p) * 5 + i1_t5];
                if (has2) {
                    b = t2 * 2 + i2_b2; p = b & 15; nb = b >> 4;
                    idx_s[fr][ptid + 128] = i2_ty
                        + path_input[(((i2_a << 9) + nb) * 16 + p) * 5 + i2_t5];
                }
            }
        }

        __syncthreads();

        // ---- store this tile's output ----
        if (tid < 128) {
            float m = fmaxf(red[fr][ow1][occ_], red[fr][ow1 + 1][occ_]);
            out[(long long)(tile * 2 + ob2) * 64 + oc] = m + bias;
        }
    }
}

extern "C" void kernel_launch(void* const* d_in, const int* in_sizes, int n_in,
                              void* d_out, int out_size) {
    const int*   path_input = (const int*)d_in[0];
    const int*   path_type  = (const int*)d_in[1];
    const float* tables     = (const float*)d_in[2];
    const float* conv_w     = (const float*)d_in[3];
    const float* conv_b     = (const float*)d_in[4];
    float* out = (float*)d_out;

    cudaFuncSetAttribute(path_emb_hmma,
                         cudaFuncAttributeMaxDynamicSharedMemorySize, SM_TOT);

    path_emb_hmma<<<NPERS, 384, SM_TOT>>>(path_input, path_type, tables,
                                          conv_w, conv_b, out);
}